// round 12
// baseline (speedup 1.0000x reference)
#include <cuda_runtime.h>

// ---------------- problem constants ----------------
#define PP        0.075f
#define HH        1440
#define WW        1440
#define GZ        32
#define GT        10
#define VZ        0.25f
#define VT        0.05f
#define ZCENTER   4.0f
#define TZCENTER  5.0f
#define CC        64

#define HWC       (HH*WW)                 // 2,073,600
#define W2        (2*HWC/32)              // 129,600 real words
#define W3        (2*HWC*GZ/32)           // 4,147,200
#define WT        (2*HWC*GT/32)           // 1,296,000

// tile/bucket layout: sections padded to full 16384-word tiles so every
// tile is full-width and bucket-aligned (padded words stay zero forever).
#define TILE_W    16384
#define WPT       16
#define BKT       1024
#define T2        8                        // ceil(W2/TILE_W)
#define T3        254                      // ceil(W3/TILE_W)
#define TT        80                       // ceil(WT/TILE_W)
#define TOT_TILES (T2+T3+TT)               // 342
#define S2        (T2*TILE_W)              // 131,072
#define S3        (T3*TILE_W)              // 4,161,536
#define ST        (TT*TILE_W)              // 1,310,720
#define OFF2      0
#define OFF3      (S2)
#define OFFT      (S2+S3)
#define TOTWP     (S2+S3+ST)               // 5,603,328
#define NBKT      (TOTWP/BKT)              // 5472
#define B2OFF     0
#define B3OFF     (S2/BKT)                 // 128
#define BTOFF     ((S2+S3)/BKT)            // 4192

#define PTS       64                       // points per block in point role
#define NUTIL     8                        // util blocks in k_point

// ---------------- scratch (no cudaMalloc allowed) ----------------
// Invariants at entry to kernel_launch:
//   g_bm   all-zero (zero-init; k_woff zeroes every nonzero word each run)
//   g_bcnt all-zero (zero-init; k_point util role zeroes it each run)
// g_woff/g_bm2/g_cnt are written-before-read within each run.
__device__ unsigned g_bm[TOTWP];
__device__ unsigned g_bm2[TOTWP];
__device__ unsigned g_woff[TOTWP];
__device__ unsigned g_bcnt[NBKT];
__device__ unsigned g_cnt[3];

// ---------------- key computation ----------------
// XLA folds divide-by-constant into multiply-by-reciprocal (f32 RN folded).
__device__ __forceinline__ void keys_from_vals(float x, float y, float z, float t, int b,
                                               int& k2, int& k3, int& kt,
                                               int& ix, int& iy)
{
    ix = (int)(x * (1.0f/PP));
    iy = (int)(y * (1.0f/PP));
    int iz = (int)(z * (1.0f/VZ));
    int it = (int)(t * (1.0f/VT));
    int base = (b*HH + iy)*WW + ix;
    k2 = base;
    k3 = base*GZ + iz;
    kt = base*GT + it;
}

__device__ __forceinline__ void compute_keys(const float* __restrict__ xyzt,
                                             int i, int c0,
                                             int& k2, int& k3, int& kt,
                                             float& x, float& y, float& z, float& t,
                                             int& ix, int& iy)
{
    x = xyzt[(size_t)i*5+0];
    y = xyzt[(size_t)i*5+1];
    z = xyzt[(size_t)i*5+2];
    t = xyzt[(size_t)i*5+4];
    int b = (i < c0) ? 0 : 1;
    keys_from_vals(x, y, z, t, b, k2, k3, kt, ix, iy);
}

// ---------------- kernels ----------------
// mark: atomicOr; the unique thread that flips a bit 0->1 bumps its bucket
// counter — exact per-bucket popcounts with no bitmap sweep.
__device__ __forceinline__ void mark_one(int w, unsigned bit)
{
    unsigned old = atomicOr(&g_bm[w], bit);
    if (!(old & bit)) atomicAdd(&g_bcnt[w >> 10], 1u);
}

__global__ __launch_bounds__(256) void k_mark(const float* __restrict__ xyzt,
                                              const int* __restrict__ cnt, int n)
{
    int i = blockIdx.x*256 + threadIdx.x;
    if (i >= n) return;
    int c0 = cnt[0];
    int k2, k3, kt, ix, iy; float x,y,z,t;
    compute_keys(xyzt, i, c0, k2, k3, kt, x, y, z, t, ix, iy);
    mark_one(OFF2 + (k2 >> 5), 1u << (k2 & 31));
    mark_one(OFF3 + (k3 >> 5), 1u << (k3 & 31));
    mark_one(OFFT + (kt >> 5), 1u << (kt & 31));
}

// woff: bucket-prefix + single bitmap read + per-word offsets + snapshot +
// inline coord emit + bitmap zeroing + section totals. One block per tile.
__global__ __launch_bounds__(1024) void k_woff(float* __restrict__ out, int n)
{
    __shared__ unsigned s_bcnt[NBKT];      // 21.9 KB
    __shared__ unsigned s_warp[32];
    __shared__ unsigned s_total;
    __shared__ unsigned s_prefix;

    int tk = blockIdx.x;
    int secid, sb0, ntile0;                // section id, first bucket, first tile
    if (tk < T2)           { secid = 0; sb0 = B2OFF; ntile0 = 0; }
    else if (tk < T2+T3)   { secid = 1; sb0 = B3OFF; ntile0 = T2; }
    else                   { secid = 2; sb0 = BTOFF; ntile0 = T2+T3; }
    int last_tk = (secid == 0) ? T2-1 : (secid == 1) ? T2+T3-1 : TOT_TILES-1;

    for (int j = threadIdx.x; j < NBKT; j += 1024) s_bcnt[j] = g_bcnt[j];
    __syncthreads();

    unsigned lane = threadIdx.x & 31, wid = threadIdx.x >> 5;
    if (wid == 0) {
        // rank prefix at tile start = sum of section buckets before this tile
        unsigned p = 0;
        int gb0 = tk * (TILE_W/BKT);       // first bucket of this tile (global)
        for (int j = sb0 + (int)lane; j < gb0; j += 32) p += s_bcnt[j];
        #pragma unroll
        for (int o = 16; o > 0; o >>= 1) p += __shfl_down_sync(0xffffffffu, p, o);
        if (lane == 0) s_prefix = p;
    }

    int base_w = tk*TILE_W + (int)threadIdx.x*WPT;   // global padded index
    unsigned bw[WPT];
    unsigned tsum = 0;
    #pragma unroll
    for (int q = 0; q < 4; q++) {
        uint4 v = *reinterpret_cast<const uint4*>(&g_bm[base_w + q*4]);
        bw[q*4+0] = v.x; bw[q*4+1] = v.y; bw[q*4+2] = v.z; bw[q*4+3] = v.w;
        tsum += __popc(v.x) + __popc(v.y) + __popc(v.z) + __popc(v.w);
    }

    unsigned incl = tsum;
    #pragma unroll
    for (int o = 1; o < 32; o <<= 1) {
        unsigned v = __shfl_up_sync(0xffffffffu, incl, o);
        if (lane >= (unsigned)o) incl += v;
    }
    if (lane == 31) s_warp[wid] = incl;
    __syncthreads();
    if (wid == 0) {
        unsigned v = s_warp[lane];
        unsigned si = v;
        #pragma unroll
        for (int o = 1; o < 32; o <<= 1) {
            unsigned tv = __shfl_up_sync(0xffffffffu, si, o);
            if (lane >= (unsigned)o) si += tv;
        }
        s_warp[lane] = si - v;
        if (lane == 31) s_total = si;
    }
    __syncthreads();
    unsigned texcl = incl - tsum + s_warp[wid];

    if (threadIdx.x == 0 && tk == last_tk)
        g_cnt[secid] = s_prefix + s_total;

    unsigned run = s_prefix + texcl;
    size_t O_C3 = (size_t)74*n;
    size_t O_CT = (size_t)149*n;

    if (secid == 0) {                       // block-uniform branch
        #pragma unroll
        for (int j = 0; j < WPT; j++) {
            unsigned m = bw[j];
            if (m) {
                int gw = base_w + j;
                g_woff[gw] = run;
                g_bm2[gw]  = m;
                g_bm[gw]   = 0u;            // restore invariant
                int vbase = (gw - OFF2) * 32;
                unsigned rank = run;
                while (m) {
                    int b = __ffs(m) - 1; m &= m - 1;
                    int v = vbase + b;
                    int pb  = v / HWC;
                    int rem = v % HWC;
                    float* row = out + (size_t)rank*3;
                    row[0] = (float)pb; row[1] = (float)(rem / WW); row[2] = (float)(rem % WW);
                    rank++;
                }
                run = rank;
            }
        }
    } else if (secid == 1) {
        #pragma unroll
        for (int j = 0; j < WPT; j++) {
            unsigned m = bw[j];
            if (m) {
                int gw = base_w + j;
                g_woff[gw] = run;
                g_bm2[gw]  = m;
                g_bm[gw]   = 0u;
                int vbase = (gw - OFF3) * 32;
                unsigned rank = run;
                while (m) {
                    int b = __ffs(m) - 1; m &= m - 1;
                    int v = vbase + b;
                    int vb = v / (HWC*GZ);
                    int r  = v % (HWC*GZ);
                    int vy = r / (WW*GZ);
                    r      = r % (WW*GZ);
                    float* row = out + O_C3 + (size_t)rank*4;
                    row[0] = (float)vb; row[1] = (float)(r % GZ); row[2] = (float)vy; row[3] = (float)(r / GZ);
                    rank++;
                }
                run = rank;
            }
        }
    } else {
        #pragma unroll
        for (int j = 0; j < WPT; j++) {
            unsigned m = bw[j];
            if (m) {
                int gw = base_w + j;
                g_woff[gw] = run;
                g_bm2[gw]  = m;
                g_bm[gw]   = 0u;
                int vbase = (gw - OFFT) * 32;
                unsigned rank = run;
                while (m) {
                    int b = __ffs(m) - 1; m &= m - 1;
                    int v = vbase + b;
                    int tb = v / (HWC*GT);
                    int r  = v % (HWC*GT);
                    int ty = r / (WW*GT);
                    r      = r % (WW*GT);
                    float* row = out + O_CT + (size_t)rank*4;
                    row[0] = (float)tb; row[1] = (float)(r % GT); row[2] = (float)ty; row[3] = (float)(r / GT);
                    rank++;
                }
                run = rank;
            }
        }
    }
}

// ---------------- util role: tailfill + bucket reset ----------------
__device__ __forceinline__ void util_role(int uid, float* __restrict__ out, int n)
{
    int gid = uid*256 + (int)threadIdx.x;
    int stride = NUTIL*256;

    for (int j = gid; j < NBKT; j += stride) g_bcnt[j] = 0u;   // next-run invariant

    unsigned c2 = g_cnt[0], c3 = g_cnt[1], ct = g_cnt[2];
    int lenA = 3*n - 3*(int)c2;
    float* a = out + (size_t)3*c2;
    for (int j = gid; j < lenA; j += stride) a[j] = -1.0f;
    int lenB = 4*n - 4*(int)c3;
    float* b = out + (size_t)74*n + (size_t)4*c3;
    for (int j = gid; j < lenB; j += stride) b[j] = -1.0f;
    int lenC = 4*n - 4*(int)ct;
    float* c = out + (size_t)149*n + (size_t)4*ct;
    for (int j = gid; j < lenC; j += stride) c[j] = -1.0f;
}

// point kernel: blocks 0..NUTIL-1 = util role, rest = 64-point feature blocks.
__global__ __launch_bounds__(256, 8) void k_point(const float* __restrict__ xyzt,
                                                  const int* __restrict__ cnt,
                                                  const float* __restrict__ pf,
                                                  float* __restrict__ out, int n)
{
    __shared__ __align__(16) float s_F[PTS*70];
    __shared__ float s_tv[PTS];     // t
    __shared__ float s_td[PTS];     // t - TZCENTER
    __shared__ int   s_k2[PTS], s_k3[PTS], s_kt[PTS];

    int b = blockIdx.x;
    if (b < NUTIL) {
        util_role(b, out, n);
        return;
    }
    int pid = b - NUTIL;

    int i0 = pid * PTS;
    if (i0 >= n) return;
    int npts = n - i0; if (npts > PTS) npts = PTS;
    int tid = threadIdx.x;
    int c0 = cnt[0];

    // stage pf (vector loads, scalar smem stores)
    const float4* pf4 = reinterpret_cast<const float4*>(pf + (size_t)i0*CC);
    for (int u = tid; u < npts*(CC/4); u += 256) {
        float4 v = pf4[u];
        int p = u >> 4;
        int c = (u & 15) * 4;
        float* d = s_F + p*70 + c;
        d[0] = v.x; d[1] = v.y; d[2] = v.z; d[3] = v.w;
    }
    // geometry + keys
    if (tid < npts) {
        int i = i0 + tid;
        int k2, k3, kt, ix, iy; float x,y,z,t;
        compute_keys(xyzt, i, c0, k2, k3, kt, x, y, z, t, ix, iy);
        s_k2[tid] = k2; s_k3[tid] = k3; s_kt[tid] = kt;
        float cx = (ix + 0.5f) * PP;
        float cy = (iy + 0.5f) * PP;
        float* r = s_F + tid*70;
        r[64] = x; r[65] = y; r[66] = z;
        r[67] = x - cx; r[68] = y - cy; r[69] = z - ZCENTER;
        s_tv[tid] = t; s_td[tid] = t - TZCENTER;
    }
    __syncthreads();

    // three rank lookups per point (g_bm2 snapshot; nothing races it)
    if (tid < 3*npts) {
        int sec = (tid < npts) ? 0 : (tid < 2*npts ? 1 : 2);
        int p = tid - sec*npts;
        int k   = (sec == 0) ? s_k2[p] : (sec == 1) ? s_k3[p] : s_kt[p];
        int off = (sec == 0) ? OFF2 : (sec == 1) ? OFF3 : OFFT;
        size_t dst = (sec == 0) ? (size_t)3*n : (sec == 1) ? (size_t)78*n : (size_t)153*n;
        int w = off + (k >> 5), bb = k & 31;
        unsigned inv = g_woff[w] + (unsigned)__popc(g_bm2[w] & ((1u << bb) - 1u));
        out[dst + i0 + p] = (float)inv;
    }

    int E = npts*70;
    float* fb = out + (size_t)4*n   + (size_t)i0*70;
    float* zb = out + (size_t)79*n  + (size_t)i0*70;
    float* tb = out + (size_t)154*n + (size_t)i0*70;

    if ((n & 3) == 0) {   // all bases 16B-aligned
        const float4* s4 = reinterpret_cast<const float4*>(s_F);
        float4* f4 = reinterpret_cast<float4*>(fb);
        float4* z4 = reinterpret_cast<float4*>(zb);
        float4* t4 = reinterpret_cast<float4*>(tb);
        int E4 = E >> 2;
        for (int u = tid; u < E4; u += 256) {
            float4 v = s4[u];
            f4[u] = v;
            z4[u] = v;
            int e = u << 2;
            int p = e / 70;
            int r = e - p*70;
            if (r == 64)      { v.z = s_tv[p]; }
            else if (r == 66) { v.x = s_tv[p]; v.w = s_td[p]; }
            else if (r == 68) { v.y = s_td[p]; }
            t4[u] = v;
        }
        int rem = E & 3;   // 0 or 2 (70*npts)
        if (rem && tid == 0) {
            int e = E - 2;
            float v0 = s_F[e], v1 = s_F[e+1];
            fb[e] = v0; fb[e+1] = v1;
            zb[e] = v0; zb[e+1] = v1;
            tb[e] = v0; tb[e+1] = s_td[npts-1];
        }
    } else {               // generic scalar fallback
        for (int e = tid; e < E; e += 256) {
            float v = s_F[e];
            fb[e] = v;
            zb[e] = v;
            int p = e / 70;
            int r = e - p*70;
            float vt = (r == 66) ? s_tv[p] : (r == 69) ? s_td[p] : v;
            tb[e] = vt;
        }
    }
}

// ---------------- launch ----------------
extern "C" void kernel_launch(void* const* d_in, const int* in_sizes, int n_in,
                              void* d_out, int out_size)
{
    const float* xyzt = (const float*)d_in[0];
    const int*   cnt  = (const int*)d_in[1];
    const float* pf   = (const float*)d_in[2];
    float*       out  = (float*)d_out;
    int n = in_sizes[0] / 5;

    // 1) mark occupied bins + first-setter bucket counts
    k_mark<<<(n + 255)/256, 256>>>(xyzt, cnt, n);
    // 2) bucket-prefix scan + offsets + snapshot + inline emit + bm cleanup
    k_woff<<<TOT_TILES, 1024>>>(out, n);
    // 3) point features + util role (tailfill + bucket reset)
    {
        int NP = (n + PTS - 1)/PTS;
        k_point<<<NP + NUTIL, 256>>>(xyzt, cnt, pf, out, n);
    }
}

// round 13
// speedup vs baseline: 1.8180x; 1.8180x over previous
#include <cuda_runtime.h>

// ---------------- problem constants ----------------
#define PP        0.075f
#define HH        1440
#define WW        1440
#define GZ        32
#define GT        10
#define VZ        0.25f
#define VT        0.05f
#define ZCENTER   4.0f
#define TZCENTER  5.0f
#define CC        64

#define HWC       (HH*WW)                 // 2,073,600
#define W2        (2*HWC/32)              // 129,600
#define W3        (2*HWC*GZ/32)           // 4,147,200
#define WT        (2*HWC*GT/32)           // 1,296,000
#define OFF2      0
#define OFF3      (W2)
#define OFFT      (W2+W3)
#define TOTW      (W2+W3+WT)              // 5,572,800

// scan tiles: 4096 words per 256-thread scan-role block (16 words / thread)
#define TILE_W    4096
#define WPT       16
#define T2        ((W2+TILE_W-1)/TILE_W)  // 32
#define T3        ((W3+TILE_W-1)/TILE_W)  // 1013
#define TT        ((WT+TILE_W-1)/TILE_W)  // 317
#define TOT_TILES (T2+T3+TT)              // 1362

#define FLAG_AGG  (1ULL<<32)
#define FLAG_PRE  (2ULL<<32)

#define PTS       64                       // points per drain block
#define LISTCAP   600064                   // >= 3*N nonzero words

// ---------------- scratch (no cudaMalloc allowed) ----------------
// Invariants at entry to kernel_launch:
//   g_bm all-zero (zero-init at load; k_final's emit zeroes listed words)
//   g_ts/g_ticket/g_nnz reset by k_mark (before this run's scan role)
__device__ unsigned g_bm[TOTW];
__device__ unsigned g_bm2[TOTW];
__device__ unsigned g_woff[TOTW];
__device__ uint2    g_list[LISTCAP];
__device__ unsigned long long g_ts[TOT_TILES];
__device__ unsigned g_ticket;
__device__ unsigned g_nnz;
__device__ unsigned g_cnt[3];

// ---------------- key computation ----------------
// XLA folds divide-by-constant into multiply-by-reciprocal (f32 RN folded).
__device__ __forceinline__ void keys_from_vals(float x, float y, float z, float t, int b,
                                               int& k2, int& k3, int& kt,
                                               int& ix, int& iy)
{
    ix = (int)(x * (1.0f/PP));
    iy = (int)(y * (1.0f/PP));
    int iz = (int)(z * (1.0f/VZ));
    int it = (int)(t * (1.0f/VT));
    int base = (b*HH + iy)*WW + ix;
    k2 = base;
    k3 = base*GZ + iz;
    kt = base*GT + it;
}

__device__ __forceinline__ void compute_keys(const float* __restrict__ xyzt,
                                             int i, int c0,
                                             int& k2, int& k3, int& kt,
                                             float& x, float& y, float& z, float& t,
                                             int& ix, int& iy)
{
    x = xyzt[(size_t)i*5+0];
    y = xyzt[(size_t)i*5+1];
    z = xyzt[(size_t)i*5+2];
    t = xyzt[(size_t)i*5+4];
    int b = (i < c0) ? 0 : 1;
    keys_from_vals(x, y, z, t, b, k2, k3, kt, ix, iy);
}

// ---------------- kernels ----------------
// mark: resultless atomicOr (REDG fire-and-forget) + state resets.
__global__ __launch_bounds__(256) void k_mark(const float* __restrict__ xyzt,
                                              const int* __restrict__ cnt, int n)
{
    int i = blockIdx.x*256 + threadIdx.x;
    if (i < TOT_TILES) g_ts[i] = 0ULL;
    if (i == 0) { g_ticket = 0u; g_nnz = 0u; }
    if (i >= n) return;
    int c0 = cnt[0];
    int k2, k3, kt, ix, iy; float x,y,z,t;
    compute_keys(xyzt, i, c0, k2, k3, kt, x, y, z, t, ix, iy);
    atomicOr(&g_bm[OFF2 + (k2 >> 5)], 1u << (k2 & 31));
    atomicOr(&g_bm[OFF3 + (k3 >> 5)], 1u << (k3 & 31));
    atomicOr(&g_bm[OFFT + (kt >> 5)], 1u << (kt & 31));
}

// ---------------- scan role (256 threads, ticket + decoupled lookback) ----
__device__ void scan_role()
{
    __shared__ unsigned s_warp[8];
    __shared__ unsigned s_total;
    __shared__ unsigned s_prefix;
    __shared__ unsigned s_tk;

    if (threadIdx.x == 0) s_tk = atomicAdd(&g_ticket, 1u);
    __syncthreads();
    unsigned tk = s_tk;
    if (tk >= TOT_TILES) return;          // extra taker, ticket unused

    int tile, secw0, words, stat0, secid, ntiles;
    if (tk < T2)           { tile = tk;           secw0 = OFF2; words = W2; stat0 = 0;     secid = 0; ntiles = T2; }
    else if (tk < T2+T3)   { tile = tk - T2;      secw0 = OFF3; words = W3; stat0 = T2;    secid = 1; ntiles = T3; }
    else                   { tile = tk - T2 - T3; secw0 = OFFT; words = WT; stat0 = T2+T3; secid = 2; ntiles = TT; }

    int base_w = tile*TILE_W + (int)threadIdx.x*WPT;
    unsigned bw[WPT];
    unsigned tsum = 0;
    #pragma unroll
    for (int q = 0; q < 4; q++) {
        int off = base_w + q*4;                   // section sizes are mod-4
        if (off < words) {
            uint4 v = *reinterpret_cast<const uint4*>(&g_bm[secw0 + off]);
            bw[q*4+0] = v.x; bw[q*4+1] = v.y; bw[q*4+2] = v.z; bw[q*4+3] = v.w;
        } else {
            bw[q*4+0] = bw[q*4+1] = bw[q*4+2] = bw[q*4+3] = 0u;
        }
        tsum += __popc(bw[q*4+0]) + __popc(bw[q*4+1]) + __popc(bw[q*4+2]) + __popc(bw[q*4+3]);
    }

    unsigned lane = threadIdx.x & 31, wid = threadIdx.x >> 5;
    unsigned incl = tsum;
    #pragma unroll
    for (int o = 1; o < 32; o <<= 1) {
        unsigned v = __shfl_up_sync(0xffffffffu, incl, o);
        if (lane >= (unsigned)o) incl += v;
    }
    if (lane == 31) s_warp[wid] = incl;
    __syncthreads();
    if (wid == 0 && lane < 8) {
        unsigned v = s_warp[lane];
        unsigned si = v;
        #pragma unroll
        for (int o = 1; o < 8; o <<= 1) {
            unsigned tv = __shfl_up_sync(0xffu, si, o);
            if (lane >= (unsigned)o) si += tv;
        }
        s_warp[lane] = si - v;
        if (lane == 7) s_total = si;
    }
    __syncthreads();
    unsigned texcl = incl - tsum + s_warp[wid];
    unsigned agg = s_total;

    // decoupled lookback (warp 0); ticket order guarantees predecessors run
    if (wid == 0) {
        if (tile == 0) {
            if (lane == 0) {
                __threadfence();
                atomicExch(&g_ts[stat0], FLAG_PRE | (unsigned long long)agg);
                s_prefix = 0u;
            }
        } else {
            if (lane == 0) {
                __threadfence();
                atomicExch(&g_ts[stat0 + tile], FLAG_AGG | (unsigned long long)agg);
            }
            unsigned prefix = 0u;
            int idx = tile - 1;
            while (true) {
                int my = idx - (int)lane;
                unsigned long long st = (my >= 0)
                    ? atomicAdd(&g_ts[stat0 + my], 0ULL)
                    : FLAG_PRE;
                unsigned flag = (unsigned)(st >> 32);
                unsigned ready = __ballot_sync(0xffffffffu, flag != 0u);
                if (ready != 0xffffffffu) continue;
                unsigned preds = __ballot_sync(0xffffffffu, flag == 2u);
                if (preds) {
                    int fp = __ffs(preds) - 1;
                    unsigned val = (lane <= (unsigned)fp) ? (unsigned)st : 0u;
                    #pragma unroll
                    for (int o = 16; o > 0; o >>= 1)
                        val += __shfl_down_sync(0xffffffffu, val, o);
                    prefix += __shfl_sync(0xffffffffu, val, 0);
                    break;
                } else {
                    unsigned val = (my >= 0) ? (unsigned)st : 0u;
                    #pragma unroll
                    for (int o = 16; o > 0; o >>= 1)
                        val += __shfl_down_sync(0xffffffffu, val, o);
                    prefix += __shfl_sync(0xffffffffu, val, 0);
                    idx -= 32;
                }
            }
            if (lane == 0) {
                __threadfence();
                atomicExch(&g_ts[stat0 + tile],
                           FLAG_PRE | (unsigned long long)(prefix + agg));
                s_prefix = prefix;
            }
        }
    }
    __syncthreads();

    if (threadIdx.x == 0 && tile == ntiles - 1)
        g_cnt[secid] = s_prefix + s_total;

    // predicated per-word offsets + snapshot + unordered list
    unsigned run = s_prefix + texcl;
    unsigned mycnt = 0;
    #pragma unroll
    for (int j = 0; j < WPT; j++) {
        if (base_w + j < words && bw[j]) {
            g_woff[secw0 + base_w + j] = run;
            g_bm2[secw0 + base_w + j]  = bw[j];
            mycnt++;
        }
        run += __popc(bw[j]);
    }
    unsigned cincl = mycnt;
    #pragma unroll
    for (int o = 1; o < 32; o <<= 1) {
        unsigned v = __shfl_up_sync(0xffffffffu, cincl, o);
        if (lane >= (unsigned)o) cincl += v;
    }
    unsigned wtot = __shfl_sync(0xffffffffu, cincl, 31);
    unsigned lbase = 0;
    if (lane == 0 && wtot) lbase = atomicAdd(&g_nnz, wtot);
    lbase = __shfl_sync(0xffffffffu, lbase, 0);
    unsigned pos = lbase + cincl - mycnt;
    #pragma unroll
    for (int j = 0; j < WPT; j++) {
        if (base_w + j < words && bw[j]) {
            g_list[pos] = make_uint2((unsigned)(secw0 + base_w + j), bw[j]);
            pos++;
        }
    }
}

// k_mid: interleaved roles. b%3==0 -> scan role (ticketed, no dependence on
// drain); else drain role pid = b - b/3 - 1 (bijective onto 0..NP-1).
// Scan's latency-bound sweep hides under the drain's BW-bound stores.
__global__ __launch_bounds__(256, 8) void k_mid(const float* __restrict__ xyzt,
                                                const int* __restrict__ cnt,
                                                const float* __restrict__ pf,
                                                float* __restrict__ out, int n)
{
    __shared__ __align__(16) float s_F[PTS*70];
    __shared__ float s_tv[PTS];
    __shared__ float s_td[PTS];

    int b = blockIdx.x;
    if (b % 3 == 0) { scan_role(); return; }
    int pid = b - b/3 - 1;

    int i0 = pid * PTS;
    if (i0 >= n) return;
    int npts = n - i0; if (npts > PTS) npts = PTS;
    int tid = threadIdx.x;
    int c0 = cnt[0];

    // stage pf
    const float4* pf4 = reinterpret_cast<const float4*>(pf + (size_t)i0*CC);
    for (int u = tid; u < npts*(CC/4); u += 256) {
        float4 v = pf4[u];
        int p = u >> 4;
        int c = (u & 15) * 4;
        float* d = s_F + p*70 + c;
        d[0] = v.x; d[1] = v.y; d[2] = v.z; d[3] = v.w;
    }
    // geometry
    if (tid < npts) {
        int i = i0 + tid;
        int k2, k3, kt, ix, iy; float x,y,z,t;
        compute_keys(xyzt, i, c0, k2, k3, kt, x, y, z, t, ix, iy);
        float cx = (ix + 0.5f) * PP;
        float cy = (iy + 0.5f) * PP;
        float* r = s_F + tid*70;
        r[64] = x; r[65] = y; r[66] = z;
        r[67] = x - cx; r[68] = y - cy; r[69] = z - ZCENTER;
        s_tv[tid] = t; s_td[tid] = t - TZCENTER;
    }
    __syncthreads();

    int E = npts*70;
    float* fb = out + (size_t)4*n   + (size_t)i0*70;
    float* zb = out + (size_t)79*n  + (size_t)i0*70;
    float* tb = out + (size_t)154*n + (size_t)i0*70;

    if ((n & 3) == 0) {
        const float4* s4 = reinterpret_cast<const float4*>(s_F);
        float4* f4 = reinterpret_cast<float4*>(fb);
        float4* z4 = reinterpret_cast<float4*>(zb);
        float4* t4 = reinterpret_cast<float4*>(tb);
        int E4 = E >> 2;
        for (int u = tid; u < E4; u += 256) {
            float4 v = s4[u];
            f4[u] = v;
            z4[u] = v;
            int e = u << 2;
            int p = e / 70;
            int r = e - p*70;
            if (r == 64)      { v.z = s_tv[p]; }
            else if (r == 66) { v.x = s_tv[p]; v.w = s_td[p]; }
            else if (r == 68) { v.y = s_td[p]; }
            t4[u] = v;
        }
        int rem = E & 3;   // 0 or 2
        if (rem && tid == 0) {
            int e = E - 2;
            float v0 = s_F[e], v1 = s_F[e+1];
            fb[e] = v0; fb[e+1] = v1;
            zb[e] = v0; zb[e+1] = v1;
            tb[e] = v0; tb[e+1] = s_td[npts-1];
        }
    } else {
        for (int e = tid; e < E; e += 256) {
            float v = s_F[e];
            fb[e] = v;
            zb[e] = v;
            int p = e / 70;
            int r = e - p*70;
            float vt = (r == 66) ? s_tv[p] : (r == 69) ? s_td[p] : v;
            tb[e] = vt;
        }
    }
}

// k_final: per-point ranks + list-driven emit (+bm cleanup) + tailfill.
__global__ __launch_bounds__(256) void k_final(const float* __restrict__ xyzt,
                                               const int* __restrict__ cnt,
                                               float* __restrict__ out, int n)
{
    int gid = blockIdx.x*256 + threadIdx.x;
    int stride = gridDim.x*256;
    int c0 = cnt[0];

    // ranks
    for (int i = gid; i < n; i += stride) {
        int k2, k3, kt, ix, iy; float x,y,z,t;
        compute_keys(xyzt, i, c0, k2, k3, kt, x, y, z, t, ix, iy);
        int w2 = OFF2 + (k2 >> 5), b2 = k2 & 31;
        int w3 = OFF3 + (k3 >> 5), b3 = k3 & 31;
        int wt = OFFT + (kt >> 5), bt = kt & 31;
        unsigned i2 = g_woff[w2] + (unsigned)__popc(g_bm2[w2] & ((1u << b2) - 1u));
        unsigned i3 = g_woff[w3] + (unsigned)__popc(g_bm2[w3] & ((1u << b3) - 1u));
        unsigned it = g_woff[wt] + (unsigned)__popc(g_bm2[wt] & ((1u << bt) - 1u));
        out[(size_t)3*n   + i] = (float)i2;
        out[(size_t)78*n  + i] = (float)i3;
        out[(size_t)153*n + i] = (float)it;
    }

    // tail fill
    {
        unsigned c2 = g_cnt[0], c3 = g_cnt[1], ct = g_cnt[2];
        int lenA = 3*n - 3*(int)c2;
        float* a = out + (size_t)3*c2;
        for (int j = gid; j < lenA; j += stride) a[j] = -1.0f;
        int lenB = 4*n - 4*(int)c3;
        float* bp = out + (size_t)74*n + (size_t)4*c3;
        for (int j = gid; j < lenB; j += stride) bp[j] = -1.0f;
        int lenC = 4*n - 4*(int)ct;
        float* cp = out + (size_t)149*n + (size_t)4*ct;
        for (int j = gid; j < lenC; j += stride) cp[j] = -1.0f;
    }

    // list-driven emit + bitmap cleanup
    size_t O_C3 = (size_t)74*n;
    size_t O_CT = (size_t)149*n;
    int nnz = (int)g_nnz;
    for (int e = gid; e < nnz; e += stride) {
        uint2 ent = g_list[e];
        int w = (int)ent.x;
        unsigned m = ent.y;
        g_bm[w] = 0u;
        unsigned rank = g_woff[w];
        if (w < OFF3) {
            while (m) {
                int bb = __ffs(m) - 1; m &= m - 1;
                int v = w*32 + bb;
                int pb  = v / HWC;
                int rem = v % HWC;
                float* row = out + (size_t)rank*3;
                row[0] = (float)pb; row[1] = (float)(rem / WW); row[2] = (float)(rem % WW);
                rank++;
            }
        } else if (w < OFFT) {
            int wl = w - OFF3;
            while (m) {
                int bb = __ffs(m) - 1; m &= m - 1;
                int v = wl*32 + bb;
                int vb = v / (HWC*GZ);
                int r  = v % (HWC*GZ);
                int vy = r / (WW*GZ);
                r      = r % (WW*GZ);
                float* row = out + O_C3 + (size_t)rank*4;
                row[0] = (float)vb; row[1] = (float)(r % GZ); row[2] = (float)vy; row[3] = (float)(r / GZ);
                rank++;
            }
        } else {
            int wl = w - OFFT;
            while (m) {
                int bb = __ffs(m) - 1; m &= m - 1;
                int v = wl*32 + bb;
                int tb = v / (HWC*GT);
                int r  = v % (HWC*GT);
                int ty = r / (WW*GT);
                r      = r % (WW*GT);
                float* row = out + O_CT + (size_t)rank*4;
                row[0] = (float)tb; row[1] = (float)(r % GT); row[2] = (float)ty; row[3] = (float)(r / GT);
                rank++;
            }
        }
    }
}

// ---------------- launch ----------------
extern "C" void kernel_launch(void* const* d_in, const int* in_sizes, int n_in,
                              void* d_out, int out_size)
{
    const float* xyzt = (const float*)d_in[0];
    const int*   cnt  = (const int*)d_in[1];
    const float* pf   = (const float*)d_in[2];
    float*       out  = (float*)d_out;
    int n = in_sizes[0] / 5;

    // 1) mark + state resets
    {
        int nb = (n + 255)/256;
        int need = (TOT_TILES + 255)/256;
        if (nb < need) nb = need;
        k_mark<<<nb, 256>>>(xyzt, cnt, n);
    }
    // 2) scan role || feature-drain role in one launch
    {
        int NP = (n + PTS - 1)/PTS;                 // drain blocks needed
        // T - (number of b%3==0 blocks) = NP, and scan blocks >= TOT_TILES
        int T = (3*NP + 1)/2;                       // ceil(NP*3/2)
        while (T - (T + 2)/3 < NP) T++;
        int nscan = (T + 2)/3;
        if (nscan < TOT_TILES) T = NP + TOT_TILES;  // fallback (won't trigger here)
        k_mid<<<T, 256>>>(xyzt, cnt, pf, out, n);
    }
    // 3) ranks + emit + tailfill
    k_final<<<1024, 256>>>(xyzt, cnt, out, n);
}